// round 8
// baseline (speedup 1.0000x reference)
#include <cuda_runtime.h>

// DWT (2x2 Haar): x (8,512,512,16) f32 -> 4 bands (8,256,256,16), concat [LL|LH|HL|HH].
//
// ILP-2 version: each thread produces TWO adjacent output pixels (j = 2*j2,
// 2*j2+1) for one channel chunk c4. 8 front-batched LDG.128 (two 2x2 quads,
// two rows) then 8 STG.128. Rationale: 4 structurally different kernels all
// pinned at 5.6-5.7 TB/s with DRAM~70% and all SM-side metrics idle -> we sit
// at the HBM mixed r/w efficiency floor. Coarser per-thread read/write phases
// (longer read bursts at the memory controller) and halved index overhead are
// the only remaining levers. Streaming hints: every line is touched once.

#define B_DIM 8
#define H_DIM 512
#define W_DIM 512
#define C_DIM 16

#define ROW_F4   (W_DIM * C_DIM / 4)        // 2048 float4 per input row
#define PIX_F4   (C_DIM / 4)                // 4 float4 per pixel
#define BAND_F4  (B_DIM * (H_DIM/2) * (W_DIM/2) * C_DIM / 4)   // 2,097,152
// threads: b(8) * i(256) * j2(128) * c4(4) = 1,048,576 * 4 = 4,194,304
#define TOTAL_THREADS (B_DIM * (H_DIM/2) * (W_DIM/4) * PIX_F4)

__global__ __launch_bounds__(256) void dwt_haar_kernel(
    const float4* __restrict__ x, float4* __restrict__ out)
{
    int idx = blockIdx.x * blockDim.x + threadIdx.x;
    // idx layout: [b:3][i:8][j2:7][c4:2]
    int c4 = idx & 3;
    int j2 = (idx >> 2) & 127;   // pair of output pixels
    int i  = (idx >> 9) & 255;
    int b  = idx >> 17;

    // input: pixels 4*j2 .. 4*j2+3 in rows 2i and 2i+1, chunk c4
    int base = ((b * H_DIM + 2 * i) * W_DIM + 4 * j2) * PIX_F4 + c4;

    // front-batch all 8 loads (2 quads x 4)
    float4 a0 = __ldcs(x + base);                        // (2i,   4j2)
    float4 b0 = __ldcs(x + base + PIX_F4);               // (2i,   4j2+1)
    float4 a1 = __ldcs(x + base + 2 * PIX_F4);           // (2i,   4j2+2)
    float4 b1 = __ldcs(x + base + 3 * PIX_F4);           // (2i,   4j2+3)
    float4 c0 = __ldcs(x + base + ROW_F4);               // (2i+1, 4j2)
    float4 d0 = __ldcs(x + base + ROW_F4 + PIX_F4);      // (2i+1, 4j2+1)
    float4 c1 = __ldcs(x + base + ROW_F4 + 2 * PIX_F4);  // (2i+1, 4j2+2)
    float4 d1 = __ldcs(x + base + ROW_F4 + 3 * PIX_F4);  // (2i+1, 4j2+3)

    float4 ll0, lh0, hl0, hh0, ll1, lh1, hl1, hh1;

#define BUTTER(A,B,C,D,LL,LH,HL,HH,F)                                     \
    {                                                                      \
        float s0 = A.F + D.F, s1 = B.F + C.F;                              \
        float e0 = A.F - D.F, e1 = B.F - C.F;                              \
        LL.F = (s0 + s1) * 0.5f; LH.F = (e0 - e1) * 0.5f;                  \
        HL.F = (e0 + e1) * 0.5f; HH.F = (s0 - s1) * 0.5f;                  \
    }

    BUTTER(a0,b0,c0,d0,ll0,lh0,hl0,hh0,x) BUTTER(a0,b0,c0,d0,ll0,lh0,hl0,hh0,y)
    BUTTER(a0,b0,c0,d0,ll0,lh0,hl0,hh0,z) BUTTER(a0,b0,c0,d0,ll0,lh0,hl0,hh0,w)
    BUTTER(a1,b1,c1,d1,ll1,lh1,hl1,hh1,x) BUTTER(a1,b1,c1,d1,ll1,lh1,hl1,hh1,y)
    BUTTER(a1,b1,c1,d1,ll1,lh1,hl1,hh1,z) BUTTER(a1,b1,c1,d1,ll1,lh1,hl1,hh1,w)
#undef BUTTER

    // output pixels (i, 2*j2) and (i, 2*j2+1), chunk c4
    int obase = ((b * (H_DIM/2) + i) * (W_DIM/2) + 2 * j2) * PIX_F4 + c4;

    __stcs(out + obase,                         ll0);
    __stcs(out + obase + PIX_F4,                ll1);
    __stcs(out + obase + BAND_F4,               lh0);
    __stcs(out + obase + BAND_F4 + PIX_F4,      lh1);
    __stcs(out + obase + 2 * BAND_F4,           hl0);
    __stcs(out + obase + 2 * BAND_F4 + PIX_F4,  hl1);
    __stcs(out + obase + 3 * BAND_F4,           hh0);
    __stcs(out + obase + 3 * BAND_F4 + PIX_F4,  hh1);
}

extern "C" void kernel_launch(void* const* d_in, const int* in_sizes, int n_in,
                              void* d_out, int out_size)
{
    (void)in_sizes; (void)n_in; (void)out_size;
    const float4* x = (const float4*)d_in[0];
    float4* out = (float4*)d_out;
    dwt_haar_kernel<<<TOTAL_THREADS / 256, 256>>>(x, out);
}

// round 10
// speedup vs baseline: 1.0007x; 1.0007x over previous
#include <cuda_runtime.h>

// DWT (2x2 Haar): x (8,512,512,16) f32 -> 4 bands (8,256,256,16), concat [LL|LH|HL|HH].
//
// v8 (256-bit) version: Blackwell LDG.E.256/STG.E.256. One thread per output
// pixel and c8-half: 4 x ld.global.cs.v8.f32 (the 2x2 quad, 32B each) and
// 4 x st.global.cs.v8.f32 (one per band). Halves LDG/STG count and L1tex
// wavefronts vs the float4 kernel. All accesses 32B-aligned. Streaming (.cs):
// every line touched exactly once.

#define B_DIM 8
#define H_DIM 512
#define W_DIM 512
#define C_DIM 16

#define ROW_F    (W_DIM * C_DIM)                 // 8192 floats per input row
#define PIX_F    (C_DIM)                         // 16 floats per pixel
#define BAND_F   (B_DIM * (H_DIM/2) * (W_DIM/2) * C_DIM)  // 16,777,216 floats
// threads: b(8) * i(256) * j(256) * c8(2) = 4,194,304
#define TOTAL_THREADS (B_DIM * (H_DIM/2) * (W_DIM/2) * 2)

__device__ __forceinline__ void ld_v8(const float* p, float* v)
{
    asm volatile("ld.global.cs.v8.f32 {%0,%1,%2,%3,%4,%5,%6,%7}, [%8];"
                 : "=f"(v[0]), "=f"(v[1]), "=f"(v[2]), "=f"(v[3]),
                   "=f"(v[4]), "=f"(v[5]), "=f"(v[6]), "=f"(v[7])
                 : "l"(p));
}

__device__ __forceinline__ void st_v8(float* p, const float* v)
{
    asm volatile("st.global.cs.v8.f32 [%0], {%1,%2,%3,%4,%5,%6,%7,%8};"
                 :: "l"(p),
                    "f"(v[0]), "f"(v[1]), "f"(v[2]), "f"(v[3]),
                    "f"(v[4]), "f"(v[5]), "f"(v[6]), "f"(v[7])
                 : "memory");
}

__global__ __launch_bounds__(256) void dwt_haar_kernel(
    const float* __restrict__ x, float* __restrict__ out)
{
    int idx = blockIdx.x * blockDim.x + threadIdx.x;
    // idx layout: [b:3][i:8][j:8][c8:1]
    int c8 = idx & 1;
    int j  = (idx >> 1) & 255;
    int i  = (idx >> 9) & 255;
    int b  = idx >> 17;

    // input base (floats): pixel (2i, 2j), half c8
    int base = ((b * H_DIM + 2 * i) * W_DIM + 2 * j) * PIX_F + c8 * 8;

    float va[8], vb[8], vc[8], vd[8];
    ld_v8(x + base,                  va);   // (2i,   2j)
    ld_v8(x + base + PIX_F,          vb);   // (2i,   2j+1)
    ld_v8(x + base + ROW_F,          vc);   // (2i+1, 2j)
    ld_v8(x + base + ROW_F + PIX_F,  vd);   // (2i+1, 2j+1)

    float ll[8], lh[8], hl[8], hh[8];
#pragma unroll
    for (int k = 0; k < 8; k++) {
        float s0 = va[k] + vd[k], s1 = vb[k] + vc[k];
        float e0 = va[k] - vd[k], e1 = vb[k] - vc[k];
        ll[k] = (s0 + s1) * 0.5f;
        lh[k] = (e0 - e1) * 0.5f;
        hl[k] = (e0 + e1) * 0.5f;
        hh[k] = (s0 - s1) * 0.5f;
    }

    // output base (floats): pixel (i, j), half c8
    int obase = ((b * (H_DIM/2) + i) * (W_DIM/2) + j) * PIX_F + c8 * 8;

    st_v8(out + obase,              ll);
    st_v8(out + obase + BAND_F,     lh);
    st_v8(out + obase + 2 * BAND_F, hl);
    st_v8(out + obase + 3 * BAND_F, hh);
}

extern "C" void kernel_launch(void* const* d_in, const int* in_sizes, int n_in,
                              void* d_out, int out_size)
{
    (void)in_sizes; (void)n_in; (void)out_size;
    const float* x = (const float*)d_in[0];
    float* out = (float*)d_out;
    dwt_haar_kernel<<<TOTAL_THREADS / 256, 256>>>(x, out);
}

// round 11
// speedup vs baseline: 1.0021x; 1.0014x over previous
#include <cuda_runtime.h>

// DWT (2x2 Haar): x (8,512,512,16) f32 -> 4 bands (8,256,256,16), concat [LL|LH|HL|HH].
//
// FINAL kernel (converged). Six structurally different variants (thread/f4,
// warp+SHFL, store-pin, load-pin, ILP-2, v8-256b) all land at 45.05-45.25us
// wall / ~5.7TB/s DRAM with every SM-side pipe idle: this problem sits at the
// HBM mixed read/write efficiency floor (~70% of spec for 1:1 r:w streams).
// This variant was the best measured wall time (45.056us):
//   - one thread per (b, i, j, c4-chunk): 4x LDG.128 (2x2 quad) + 4x STG.128
//     (one per band), all 16B-aligned and sector-perfect
//   - loads carry createpolicy.fractional.L2::evict_last 0.75
//   - stores are __stcs streaming (write stream never competes for L2)

#define B_DIM 8
#define H_DIM 512
#define W_DIM 512
#define C_DIM 16

#define ROW_F4   (W_DIM * C_DIM / 4)        // 2048 float4 per input row
#define PIX_F4   (C_DIM / 4)                // 4 float4 per pixel
#define BAND_F4  (B_DIM * (H_DIM/2) * (W_DIM/2) * C_DIM / 4)   // 2,097,152
#define TOTAL_THREADS (B_DIM * (H_DIM/2) * (W_DIM/2) * PIX_F4) // 8,388,608

__device__ __forceinline__ float4 ld_f4_evict_last(const float4* p, unsigned long long pol)
{
    float4 v;
    asm volatile("ld.global.L2::cache_hint.v4.f32 {%0,%1,%2,%3}, [%4], %5;"
                 : "=f"(v.x), "=f"(v.y), "=f"(v.z), "=f"(v.w)
                 : "l"(p), "l"(pol));
    return v;
}

__global__ __launch_bounds__(256) void dwt_haar_kernel(
    const float4* __restrict__ x, float4* __restrict__ out)
{
    unsigned long long pol;
    asm("createpolicy.fractional.L2::evict_last.b64 %0, 0.75;" : "=l"(pol));

    int idx = blockIdx.x * blockDim.x + threadIdx.x;
    // idx layout: [b:3][i:8][j:8][c4:2]
    int c4 = idx & 3;
    int j  = (idx >> 2) & 255;
    int i  = (idx >> 10) & 255;
    int b  = idx >> 18;

    int base = ((b * H_DIM + 2 * i) * W_DIM + 2 * j) * PIX_F4 + c4;

    float4 va = ld_f4_evict_last(x + base,                   pol); // (2i,   2j)
    float4 vb = ld_f4_evict_last(x + base + PIX_F4,          pol); // (2i,   2j+1)
    float4 vc = ld_f4_evict_last(x + base + ROW_F4,          pol); // (2i+1, 2j)
    float4 vd = ld_f4_evict_last(x + base + ROW_F4 + PIX_F4, pol); // (2i+1, 2j+1)

    // Butterfly: s0=a+d, s1=b+c, d0=a-d, d1=b-c
    // LL=(s0+s1)/2, LH=(d0-d1)/2, HL=(d0+d1)/2, HH=(s0-s1)/2
    float4 ll, lh, hl, hh;
    {
        float s0, s1, d0, d1;
        s0 = va.x + vd.x; s1 = vb.x + vc.x; d0 = va.x - vd.x; d1 = vb.x - vc.x;
        ll.x = (s0 + s1) * 0.5f; lh.x = (d0 - d1) * 0.5f;
        hl.x = (d0 + d1) * 0.5f; hh.x = (s0 - s1) * 0.5f;
        s0 = va.y + vd.y; s1 = vb.y + vc.y; d0 = va.y - vd.y; d1 = vb.y - vc.y;
        ll.y = (s0 + s1) * 0.5f; lh.y = (d0 - d1) * 0.5f;
        hl.y = (d0 + d1) * 0.5f; hh.y = (s0 - s1) * 0.5f;
        s0 = va.z + vd.z; s1 = vb.z + vc.z; d0 = va.z - vd.z; d1 = vb.z - vc.z;
        ll.z = (s0 + s1) * 0.5f; lh.z = (d0 - d1) * 0.5f;
        hl.z = (d0 + d1) * 0.5f; hh.z = (s0 - s1) * 0.5f;
        s0 = va.w + vd.w; s1 = vb.w + vc.w; d0 = va.w - vd.w; d1 = vb.w - vc.w;
        ll.w = (s0 + s1) * 0.5f; lh.w = (d0 - d1) * 0.5f;
        hl.w = (d0 + d1) * 0.5f; hh.w = (s0 - s1) * 0.5f;
    }

    int obase = ((b * (H_DIM/2) + i) * (W_DIM/2) + j) * PIX_F4 + c4;

    __stcs(out + obase,               ll);
    __stcs(out + obase + BAND_F4,     lh);
    __stcs(out + obase + 2 * BAND_F4, hl);
    __stcs(out + obase + 3 * BAND_F4, hh);
}

extern "C" void kernel_launch(void* const* d_in, const int* in_sizes, int n_in,
                              void* d_out, int out_size)
{
    (void)in_sizes; (void)n_in; (void)out_size;
    const float4* x = (const float4*)d_in[0];
    float4* out = (float4*)d_out;
    dwt_haar_kernel<<<TOTAL_THREADS / 256, 256>>>(x, out);
}